// round 9
// baseline (speedup 1.0000x reference)
#include <cuda_runtime.h>
#include <cstdint>

// SubsampledRelativeAttention (closed form, validated R1-R8):
//   h = b % 8, c = t >> 2, E = [e1 ; e2[1:]] (511 rows)
//   out[b,t,s] = q[b,t] . E[h, j],  j = 255 - c + s
// mma.sync m16n8k8 TF32 banded GEMM.
// R9: warp = 32 t-rows x full band (halves B-LDS duplication), CTA = 128
// rows, JC=32 chunks (9 per CTA) to bound accumulator registers, A frags
// register-resident, warp-private epilogue, St aliases Qs.

#define TT 1024
#define SS 256
#define DD 64

constexpr int TM   = 128;     // t rows per CTA
constexpr int JC   = 32;      // E rows per chunk
constexpr int NCH  = 9;       // 9*32 = 288 >= 287 band width (c spans 32)
constexpr int STRE = 68;      // Es/Qs stride (words)
constexpr int STRS = 40;      // St stride (words): STS.64 conflict-free
// Qs = 128*68*4 = 34816 B; St = 128*40*4 = 20480 B aliases Qs; Es after Qs.
constexpr int SMEM_BYTES = TM * STRE * 4 + JC * STRE * 4;   // 34816+8704=43520

__device__ __forceinline__ uint32_t f2tf32(float x) {
    uint32_t r;
    asm("cvt.rna.tf32.f32 %0, %1;" : "=r"(r) : "f"(x));
    return r;
}
__device__ __forceinline__ uint32_t smem_u32(const void* p) {
    uint32_t a;
    asm("{ .reg .u64 t; cvta.to.shared.u64 t, %1; cvt.u32.u64 %0, t; }"
        : "=r"(a) : "l"(p));
    return a;
}
__device__ __forceinline__ void cp_async16(uint32_t dst, const void* src) {
    asm volatile("cp.async.cg.shared.global [%0], [%1], 16;"
                 :: "r"(dst), "l"(src));
}
__device__ __forceinline__ void cp_commit() {
    asm volatile("cp.async.commit_group;" ::: "memory");
}
__device__ __forceinline__ void cp_wait0() {
    asm volatile("cp.async.wait_group 0;" ::: "memory");
}

__global__ __launch_bounds__(128, 4)
void srel_tf32_kernel(const float* __restrict__ q,
                      const float* __restrict__ e1,
                      const float* __restrict__ e2,
                      float* __restrict__ out)
{
    extern __shared__ __align__(16) uint32_t smem[];
    uint32_t* Qs = smem;                       // [128][68] tf32 (until extraction)
    float*    St = reinterpret_cast<float*>(smem);   // [128][40] (aliases Qs)
    uint32_t* Es = smem + TM * STRE;           // [32][68] raw f32 bits

    const int blk  = blockIdx.x;
    const int b    = blk >> 3;            // 8 t-tiles per batch row
    const int t0   = (blk & 7) * TM;
    const int h    = b & 7;
    const int c0   = t0 >> 2;
    const int jbase = 224 - c0;           // min j over tile (c spans c0..c0+31)

    const int tid  = threadIdx.x;
    const int wid  = tid >> 5;            // warp owns rows [wid*32, +32)
    const int lane = tid & 31;
    const int r    = lane >> 2;
    const int cidx = lane & 3;

    // warp frag window: rows span c-c0 in [8w, 8w+7] -> j_off in [24-8w, 286-8w]
    const int glo = (24 - 8 * wid) >> 3;    // 3,2,1,0
    const int ghi = (286 - 8 * wid) >> 3;   // 35,34,33,32

    const float4* e1h = reinterpret_cast<const float4*>(e1 + (size_t)h * SS * DD);
    const float4* e2h = reinterpret_cast<const float4*>(e2 + (size_t)h * SS * DD);
    const uint32_t es_base = smem_u32(Es);

    // ---- prefetch E chunk 0 ----
    {
        const int jc = jbase;
        for (int i = tid; i < JC * 16; i += 128) {
            const int row = i >> 4, c16 = i & 15;
            const int j = jc + row;
            const float4* src;
            if (j <= 255) {
                src = e1h + j * 16 + c16;            // E rows [0,255] = e1
            } else {
                int j2 = j - 255;                    // E rows [256,510] = e2[1:]
                if (j2 > 255) j2 = 255;              // overrun rows never flushed
                src = e2h + j2 * 16 + c16;
            }
            cp_async16(es_base + (row * STRE + c16 * 4) * 4, src);
        }
        cp_commit();
    }

    // ---- Q tile (128 x 64) -> smem tf32 ----
    const float4* qb4 = reinterpret_cast<const float4*>(
                            q + ((size_t)b * TT + t0) * DD);
    for (int i = tid; i < TM * DD / 4; i += 128) {
        const int row = i >> 4;
        const int k4  = (i & 15) << 2;
        const float4 v = qb4[i];
        uint4 u;
        u.x = f2tf32(v.x); u.y = f2tf32(v.y);
        u.z = f2tf32(v.z); u.w = f2tf32(v.w);
        *reinterpret_cast<uint4*>(Qs + row * STRE + k4) = u;
    }
    __syncthreads();

    // ---- extract A fragments once: 2 m-frags (rows wid*32 + mt*16 + ...) ----
    uint32_t ah[8][2][4];
    #pragma unroll
    for (int mt = 0; mt < 2; mt++) {
        const uint32_t* Aq = Qs + (wid * 32 + mt * 16 + r) * STRE + cidx;
        #pragma unroll
        for (int ks = 0; ks < 8; ks++) {
            const int k0 = ks * 8;
            ah[ks][mt][0] = Aq[k0];
            ah[ks][mt][1] = Aq[8 * STRE + k0];
            ah[ks][mt][2] = Aq[k0 + 4];
            ah[ks][mt][3] = Aq[8 * STRE + k0 + 4];
        }
    }
    cp_wait0();
    __syncthreads();   // extraction done -> Qs region free for St; Es ready

    const uint32_t* Be = Es + r * STRE + cidx;

    for (int ch = 0; ch < NCH; ch++) {
        const int jc = jbase + ch * JC;

        // ---- MMA: 4 frags per chunk, skip out-of-band (warp-uniform) ----
        float acc[4][2][4];
        #pragma unroll
        for (int nt = 0; nt < 4; nt++)
            #pragma unroll
            for (int mt = 0; mt < 2; mt++)
                #pragma unroll
                for (int v = 0; v < 4; v++)
                    acc[nt][mt][v] = 0.0f;

        #pragma unroll
        for (int nt = 0; nt < 4; nt++) {
            const int g = ch * 4 + nt;
            if (g < glo || g > ghi) continue;
            const uint32_t* p = Be + nt * 8 * STRE;
            #pragma unroll
            for (int ks = 0; ks < 8; ks++) {
                const uint32_t b0 = p[ks * 8];        // raw f32 = tf32 truncation
                const uint32_t b1 = p[ks * 8 + 4];
                #pragma unroll
                for (int mt = 0; mt < 2; mt++)
                    asm volatile(
                        "mma.sync.aligned.m16n8k8.row.col.f32.tf32.tf32.f32 "
                        "{%0,%1,%2,%3}, {%4,%5,%6,%7}, {%8,%9}, {%0,%1,%2,%3};"
                        : "+f"(acc[nt][mt][0]), "+f"(acc[nt][mt][1]),
                          "+f"(acc[nt][mt][2]), "+f"(acc[nt][mt][3])
                        : "r"(ah[ks][mt][0]), "r"(ah[ks][mt][1]),
                          "r"(ah[ks][mt][2]), "r"(ah[ks][mt][3]),
                          "r"(b0), "r"(b1));
            }
        }

        __syncthreads();   // all warps done reading Es

        // ---- prefetch next E chunk into freed Es ----
        if (ch < NCH - 1) {
            const int jcn = jbase + (ch + 1) * JC;
            for (int i = tid; i < JC * 16; i += 128) {
                const int row = i >> 4, c16 = i & 15;
                const int j = jcn + row;
                const float4* src;
                if (j <= 255) {
                    src = e1h + j * 16 + c16;
                } else {
                    int j2 = j - 255;
                    if (j2 > 255) j2 = 255;
                    src = e2h + j2 * 16 + c16;
                }
                cp_async16(es_base + (row * STRE + c16 * 4) * 4, src);
            }
            cp_commit();
        }

        // ---- warp-private stage: rows [wid*32,+32), STS.64 conflict-free ----
        #pragma unroll
        for (int mt = 0; mt < 2; mt++) {
            #pragma unroll
            for (int half = 0; half < 2; half++) {
                const int row = wid * 32 + mt * 16 + half * 8 + r;
                float* srow = St + row * STRS + 2 * cidx;
                #pragma unroll
                for (int nt = 0; nt < 4; nt++) {
                    const int g = ch * 4 + nt;
                    if (g < glo || g > ghi) continue;
                    float2 v;
                    v.x = acc[nt][mt][half * 2 + 0];
                    v.y = acc[nt][mt][half * 2 + 1];
                    *reinterpret_cast<float2*>(srow + nt * 8) = v;
                }
            }
        }
        __syncwarp();

        // ---- warp-private coalesced flush: 32 rows, lane = s offset ----
        #pragma unroll 8
        for (int i = 0; i < 32; i++) {
            const int row  = wid * 32 + i;
            const int c    = (t0 + row) >> 2;
            const int srow = jc + c - 255;
            if (srow >= SS || srow + JC <= 0) continue;
            const float v0 = St[row * STRS + lane];
            const int s0 = srow + lane;
            if ((unsigned)s0 < (unsigned)SS)
                out[((size_t)b * TT + t0 + row) * SS + s0] = v0;
        }

        if (ch < NCH - 1) {
            cp_wait0();
            __syncthreads();   // next Es visible
        }
    }
}

extern "C" void kernel_launch(void* const* d_in, const int* in_sizes, int n_in,
                              void* d_out, int out_size)
{
    const float* q  = (const float*)d_in[0];
    const float* e1 = (const float*)d_in[1];
    const float* e2 = (const float*)d_in[2];
    float* out      = (float*)d_out;

    cudaFuncSetAttribute(srel_tf32_kernel,
                         cudaFuncAttributeMaxDynamicSharedMemorySize, SMEM_BYTES);
    srel_tf32_kernel<<<128 * (TT / TM), 128, SMEM_BYTES>>>(q, e1, e2, out);
}